// round 5
// baseline (speedup 1.0000x reference)
#include <cuda_runtime.h>
#include <cstdint>

// TopK per row (B=4096 x D=65536 fp32, k=64), ReLU, scatter into zeros.
// Unidirectional memory streams:
//   1) zero_kernel   : pure-write zero fill of out    (measured 7.0 TB/s)
//   2) select_kernel : pure-read top-k -> compact buf (front-batched MLP=8)
//   3) scatter_kernel: k scattered stores per row (tiny)
// Select hot path: 8 back-to-back LDG.128 with NO intervening branches, then
// branchless threshold flags, then a rare push path. Exact multi-level
// histogram fallback for arbitrary inputs (tie-break lowest index, matching
// jax.lax.top_k).

namespace {

constexpr int TPB   = 512;
constexpr int D_DIM = 65536;
constexpr int NV    = D_DIM / 4;     // 16384 float4 per row
constexpr int U     = 8;             // front-batched loads per thread
constexpr int CAP   = 2048;          // candidate capacity (smem)
constexpr int SLOT  = 256;           // per-row winner slots in global buffer
constexpr int MAXROWS = 4096;
constexpr float THRESH = 2.5f;       // E[cnt]~407 for N(0,1), >> k=64
constexpr unsigned SMEM_BYTES = (2u * CAP + 4096u) * 4u;  // cand val+idx, hist

__device__ float    g_val[MAXROWS * SLOT];
__device__ unsigned g_idx[MAXROWS * SLOT];

__device__ __forceinline__ unsigned orderKey(float f) {
    unsigned u = __float_as_uint(f);
    return u ^ ((u & 0x80000000u) ? 0xFFFFFFFFu : 0x80000000u);
}

// ---------------------------------------------------------------- zero fill
__global__ void __launch_bounds__(TPB)
zero_kernel(float4* __restrict__ out)
{
    float4* rowp = out + (size_t)blockIdx.x * NV;
    const float4 z = make_float4(0.f, 0.f, 0.f, 0.f);
    #pragma unroll 8
    for (int i = threadIdx.x; i < NV; i += TPB)
        __stcs(&rowp[i], z);
}

// ---------------------------------------------------------------- select
__global__ void __launch_bounds__(TPB)
select_kernel(const float* __restrict__ x, const int* __restrict__ kptr)
{
    extern __shared__ unsigned smem_u[];
    float*    cval = reinterpret_cast<float*>(smem_u);   // [CAP]
    unsigned* cidx = smem_u + CAP;                        // [CAP]
    unsigned* hist = smem_u + 2 * CAP;                    // [4096] fallback
    __shared__ unsigned s_cnt, s_bin, s_rank;
    __shared__ unsigned s_chunk[TPB + 1];                 // fallback scan

    const int tid = threadIdx.x;
    const int row = blockIdx.x;
    const unsigned k = (unsigned)__ldg(kptr);
    const unsigned kw = min(k, (unsigned)SLOT);

    const float4* rowv = reinterpret_cast<const float4*>(x) + (size_t)row * NV;
    float*    gval = g_val + (size_t)row * SLOT;
    unsigned* gidx = g_idx + (size_t)row * SLOT;

    if (tid == 0) s_cnt = 0u;
    __syncthreads();

    // ---- Hot pass: front-batched pure-read stream, branchless flags ----
    // NV / (TPB*U) = 16384 / 4096 = 4 outer iterations, exact fit.
    for (int base = tid; base < NV; base += TPB * U) {
        float4 v[U];
        #pragma unroll
        for (int u = 0; u < U; ++u)               // 8 LDG.128 back-to-back
            v[u] = __ldcs(&rowv[base + u * TPB]);

        unsigned flags = 0u;
        #pragma unroll
        for (int u = 0; u < U; ++u) {             // pure ALU, no branches
            float m = fmaxf(fmaxf(v[u].x, v[u].y), fmaxf(v[u].z, v[u].w));
            flags |= (m >= THRESH) ? (1u << u) : 0u;
        }

        if (flags) {                              // rare (~1 in 5 batches)
            #pragma unroll
            for (int u = 0; u < U; ++u) {
                if (flags & (1u << u)) {
                    const int i = base + u * TPB;
                    float vv[4] = {v[u].x, v[u].y, v[u].z, v[u].w};
                    #pragma unroll
                    for (int l = 0; l < 4; ++l) {
                        if (vv[l] >= THRESH) {
                            unsigned p = atomicAdd(&s_cnt, 1u);
                            if (p < CAP) { cval[p] = vv[l]; cidx[p] = (unsigned)(i * 4 + l); }
                        }
                    }
                }
            }
        }
    }
    __syncthreads();

    const unsigned cnt = s_cnt;
    if (cnt >= k && cnt <= CAP) {
        // exact rank among candidates; rank unique -> slot position
        for (unsigned j = (unsigned)tid; j < cnt; j += TPB) {
            const float    vj = cval[j];
            const unsigned ij = cidx[j];
            unsigned rank = 0;
            for (unsigned t = 0; t < cnt; ++t) {
                const float vt = cval[t];
                rank += (vt > vj) || (vt == vj && cidx[t] < ij);
            }
            if (rank < kw) { gval[rank] = fmaxf(vj, 0.0f); gidx[rank] = ij; }
        }
        return;
    }

    // ============== Exact fallback: 3-level radix refinement ==============
    // Never runs on the benchmark distribution; correctness for any input.
    const float* rowf = reinterpret_cast<const float*>(rowv);
    unsigned need = k;
    unsigned b0 = 0, b1 = 0, b2 = 0;

    // level 0: bits[31:20]
    for (int i = tid; i < 4096; i += TPB) hist[i] = 0u;
    __syncthreads();
    for (int i = tid; i < D_DIM; i += TPB)
        atomicAdd(&hist[orderKey(rowf[i]) >> 20], 1u);
    __syncthreads();
    if (tid == 0) {
        unsigned acc = 0;
        for (int b = 4095; b >= 0; --b) {
            unsigned c = hist[b];
            if (acc + c >= need) { s_bin = (unsigned)b; s_rank = need - acc; break; }
            acc += c;
        }
    }
    __syncthreads();
    b0 = s_bin; need = s_rank;

    // level 1: bits[19:8] restricted to top bits == b0
    for (int i = tid; i < 4096; i += TPB) hist[i] = 0u;
    __syncthreads();
    for (int i = tid; i < D_DIM; i += TPB) {
        unsigned key = orderKey(rowf[i]);
        if ((key >> 20) == b0) atomicAdd(&hist[(key >> 8) & 0xFFFu], 1u);
    }
    __syncthreads();
    if (tid == 0) {
        unsigned acc = 0;
        for (int b = 4095; b >= 0; --b) {
            unsigned c = hist[b];
            if (acc + c >= need) { s_bin = (unsigned)b; s_rank = need - acc; break; }
            acc += c;
        }
    }
    __syncthreads();
    b1 = s_bin; need = s_rank;

    // level 2: bits[7:0] restricted to top 24 bits
    for (int i = tid; i < 256; i += TPB) hist[i] = 0u;
    __syncthreads();
    const unsigned pre24 = (b0 << 12) | b1;
    for (int i = tid; i < D_DIM; i += TPB) {
        unsigned key = orderKey(rowf[i]);
        if ((key >> 8) == pre24) atomicAdd(&hist[key & 0xFFu], 1u);
    }
    __syncthreads();
    if (tid == 0) {
        unsigned acc = 0;
        for (int b = 255; b >= 0; --b) {
            unsigned c = hist[b];
            if (acc + c >= need) { s_bin = (unsigned)b; s_rank = need - acc; break; }
            acc += c;
        }
        s_cnt = 0u;
    }
    __syncthreads();
    b2 = s_bin; need = s_rank;                    // take `need` of key==pivot
    const unsigned pivot = ((pre24) << 8) | b2;

    // winners with key > pivot
    for (int i = tid; i < D_DIM; i += TPB) {
        float v = rowf[i];
        unsigned key = orderKey(v);
        if (key > pivot) {
            unsigned p = atomicAdd(&s_cnt, 1u);
            if (p < kw) { gval[p] = fmaxf(v, 0.0f); gidx[p] = (unsigned)i; }
        }
    }
    __syncthreads();

    // key == pivot: take `need` with the SMALLEST indices (jax tie rule).
    {
        const int CHUNK = D_DIM / TPB;   // 128
        unsigned local = 0;
        for (int i = tid * CHUNK; i < (tid + 1) * CHUNK; ++i)
            local += (orderKey(rowf[i]) == pivot);
        s_chunk[tid + 1] = local;
        if (tid == 0) s_chunk[0] = 0;
        __syncthreads();
        if (tid == 0)
            for (int t = 1; t <= TPB; ++t) s_chunk[t] += s_chunk[t - 1];
        __syncthreads();
        unsigned ord = s_chunk[tid];
        for (int i = tid * CHUNK; i < (tid + 1) * CHUNK; ++i) {
            float v = rowf[i];
            if (orderKey(v) == pivot) {
                if (ord < need) {
                    unsigned p = atomicAdd(&s_cnt, 1u);
                    if (p < kw) { gval[p] = fmaxf(v, 0.0f); gidx[p] = (unsigned)i; }
                }
                ++ord;
            }
        }
    }
}

// ---------------------------------------------------------------- scatter
__global__ void __launch_bounds__(SLOT)
scatter_kernel(const int* __restrict__ kptr, float* __restrict__ out)
{
    const int row = blockIdx.x;
    const unsigned j = threadIdx.x;
    const unsigned k = (unsigned)__ldg(kptr);
    if (j < min(k, (unsigned)SLOT)) {
        unsigned idx = g_idx[(size_t)row * SLOT + j];
        out[(size_t)row * D_DIM + idx] = g_val[(size_t)row * SLOT + j];
    }
}

} // namespace

extern "C" void kernel_launch(void* const* d_in, const int* in_sizes, int n_in,
                              void* d_out, int out_size)
{
    const float* x   = (const float*)d_in[0];
    const int*   kp  = (const int*)d_in[1];
    float*       out = (float*)d_out;

    const int rows = in_sizes[0] / D_DIM;

    cudaFuncSetAttribute(select_kernel,
                         cudaFuncAttributeMaxDynamicSharedMemorySize, SMEM_BYTES);

    zero_kernel<<<rows, TPB>>>(reinterpret_cast<float4*>(out));
    select_kernel<<<rows, TPB, SMEM_BYTES>>>(x, kp);
    scatter_kernel<<<rows, SLOT>>>(kp, out);
}

// round 6
// speedup vs baseline: 1.5104x; 1.5104x over previous
#include <cuda_runtime.h>
#include <cstdint>

// TopK per row (B=4096 x D=65536 fp32, k=64), ReLU, scatter into zeros.
// SINGLE fused kernel, one CTA per row:
//   hot loop: 4x LDG.128 (plain) + 4x STG.128 zeros (streaming) + branchless
//             threshold flags + rare candidate push to smem
//   then: exact rank of ~407 candidates in smem, direct scatter of k winners
//         into the row this CTA just zeroed (__syncthreads orders stores).
// Exact 3-level radix fallback for arbitrary inputs (tie-break lowest index,
// matching jax.lax.top_k); never triggers on N(0,1) benchmark data.

namespace {

constexpr int TPB   = 512;
constexpr int D_DIM = 65536;
constexpr int NV    = D_DIM / 4;     // 16384 float4 per row
constexpr int U     = 4;             // interleave batch
constexpr int CAP   = 2048;          // candidate capacity (smem)
constexpr float THRESH = 2.5f;       // E[cnt]~407 for N(0,1), >> k=64
constexpr unsigned SMEM_BYTES = (2u * CAP + 4096u) * 4u;  // 32 KB

__device__ __forceinline__ unsigned orderKey(float f) {
    unsigned u = __float_as_uint(f);
    return u ^ ((u & 0x80000000u) ? 0xFFFFFFFFu : 0x80000000u);
}

__global__ void __launch_bounds__(TPB)
topk_fused_kernel(const float* __restrict__ x,
                  const int* __restrict__ kptr,
                  float* __restrict__ out)
{
    extern __shared__ unsigned smem_u[];
    float*    cval = reinterpret_cast<float*>(smem_u);    // [CAP]
    unsigned* cidx = smem_u + CAP;                        // [CAP]
    unsigned* hist = smem_u + 2 * CAP;                    // [4096] fallback
    __shared__ unsigned s_cnt, s_bin, s_rank;
    __shared__ unsigned s_chunk[TPB + 1];                 // fallback scan

    const int tid = threadIdx.x;
    const int row = blockIdx.x;
    const unsigned k = (unsigned)__ldg(kptr);

    const float4* rowv = reinterpret_cast<const float4*>(x) + (size_t)row * NV;
    float4*       outv = reinterpret_cast<float4*>(out)     + (size_t)row * NV;
    float*        outf = out + (size_t)row * D_DIM;

    if (tid == 0) s_cnt = 0u;
    __syncthreads();

    // ---- Hot pass: interleaved read + zero-write + rare collect ----
    const float4 z = make_float4(0.f, 0.f, 0.f, 0.f);
    // NV / (TPB*U) = 16384 / 2048 = 8 outer iterations, exact fit.
    for (int base = tid; base < NV; base += TPB * U) {
        float4 v[U];
        #pragma unroll
        for (int u = 0; u < U; ++u)
            v[u] = rowv[base + u * TPB];          // plain LDG.128
        #pragma unroll
        for (int u = 0; u < U; ++u)
            __stcs(&outv[base + u * TPB], z);     // streaming STG.128

        unsigned flags = 0u;
        #pragma unroll
        for (int u = 0; u < U; ++u) {
            float m = fmaxf(fmaxf(v[u].x, v[u].y), fmaxf(v[u].z, v[u].w));
            flags |= (m >= THRESH) ? (1u << u) : 0u;
        }
        if (flags) {                              // rare
            #pragma unroll
            for (int u = 0; u < U; ++u) {
                if (flags & (1u << u)) {
                    const int i = base + u * TPB;
                    float vv[4] = {v[u].x, v[u].y, v[u].z, v[u].w};
                    #pragma unroll
                    for (int l = 0; l < 4; ++l) {
                        if (vv[l] >= THRESH) {
                            unsigned p = atomicAdd(&s_cnt, 1u);
                            if (p < CAP) { cval[p] = vv[l]; cidx[p] = (unsigned)(i * 4 + l); }
                        }
                    }
                }
            }
        }
    }
    __syncthreads();   // orders this CTA's zero-stores before winner scatter

    const unsigned cnt = s_cnt;
    if (cnt >= k && cnt <= CAP) {
        // ---- Exact rank among candidates; direct scatter ----
        for (unsigned j = (unsigned)tid; j < cnt; j += TPB) {
            const float    vj = cval[j];
            const unsigned ij = cidx[j];
            unsigned rank = 0;
            for (unsigned t = 0; t < cnt; ++t) {
                const float vt = cval[t];
                rank += (vt > vj) || (vt == vj && cidx[t] < ij);
            }
            if (rank < k)
                outf[ij] = fmaxf(vj, 0.0f);
        }
        return;
    }

    // ============== Exact fallback: 3-level radix refinement ==============
    // (out row is already zeroed above; write winners directly.)
    const float* rowf = reinterpret_cast<const float*>(rowv);
    unsigned need = k;
    unsigned b0 = 0, b1 = 0, b2 = 0;

    // level 0: bits[31:20]
    for (int i = tid; i < 4096; i += TPB) hist[i] = 0u;
    __syncthreads();
    for (int i = tid; i < D_DIM; i += TPB)
        atomicAdd(&hist[orderKey(rowf[i]) >> 20], 1u);
    __syncthreads();
    if (tid == 0) {
        unsigned acc = 0;
        for (int b = 4095; b >= 0; --b) {
            unsigned c = hist[b];
            if (acc + c >= need) { s_bin = (unsigned)b; s_rank = need - acc; break; }
            acc += c;
        }
    }
    __syncthreads();
    b0 = s_bin; need = s_rank;

    // level 1: bits[19:8] restricted to top bits == b0
    for (int i = tid; i < 4096; i += TPB) hist[i] = 0u;
    __syncthreads();
    for (int i = tid; i < D_DIM; i += TPB) {
        unsigned key = orderKey(rowf[i]);
        if ((key >> 20) == b0) atomicAdd(&hist[(key >> 8) & 0xFFFu], 1u);
    }
    __syncthreads();
    if (tid == 0) {
        unsigned acc = 0;
        for (int b = 4095; b >= 0; --b) {
            unsigned c = hist[b];
            if (acc + c >= need) { s_bin = (unsigned)b; s_rank = need - acc; break; }
            acc += c;
        }
    }
    __syncthreads();
    b1 = s_bin; need = s_rank;

    // level 2: bits[7:0] restricted to top 24 bits
    for (int i = tid; i < 256; i += TPB) hist[i] = 0u;
    __syncthreads();
    const unsigned pre24 = (b0 << 12) | b1;
    for (int i = tid; i < D_DIM; i += TPB) {
        unsigned key = orderKey(rowf[i]);
        if ((key >> 8) == pre24) atomicAdd(&hist[key & 0xFFu], 1u);
    }
    __syncthreads();
    if (tid == 0) {
        unsigned acc = 0;
        for (int b = 255; b >= 0; --b) {
            unsigned c = hist[b];
            if (acc + c >= need) { s_bin = (unsigned)b; s_rank = need - acc; break; }
            acc += c;
        }
    }
    __syncthreads();
    b2 = s_bin; need = s_rank;                    // take `need` of key==pivot
    const unsigned pivot = (pre24 << 8) | b2;

    // winners with key > pivot: write directly
    for (int i = tid; i < D_DIM; i += TPB) {
        float v = rowf[i];
        if (orderKey(v) > pivot)
            outf[i] = fmaxf(v, 0.0f);
    }

    // key == pivot: take `need` with the SMALLEST indices (jax tie rule)
    {
        const int CHUNK = D_DIM / TPB;   // 128
        unsigned local = 0;
        for (int i = tid * CHUNK; i < (tid + 1) * CHUNK; ++i)
            local += (orderKey(rowf[i]) == pivot);
        s_chunk[tid + 1] = local;
        if (tid == 0) s_chunk[0] = 0;
        __syncthreads();
        if (tid == 0)
            for (int t = 1; t <= TPB; ++t) s_chunk[t] += s_chunk[t - 1];
        __syncthreads();
        unsigned ord = s_chunk[tid];
        for (int i = tid * CHUNK; i < (tid + 1) * CHUNK; ++i) {
            float v = rowf[i];
            if (orderKey(v) == pivot) {
                if (ord < need)
                    outf[i] = fmaxf(v, 0.0f);
                ++ord;
            }
        }
    }
}

} // namespace

extern "C" void kernel_launch(void* const* d_in, const int* in_sizes, int n_in,
                              void* d_out, int out_size)
{
    const float* x   = (const float*)d_in[0];
    const int*   kp  = (const int*)d_in[1];
    float*       out = (float*)d_out;

    const int rows = in_sizes[0] / D_DIM;

    cudaFuncSetAttribute(topk_fused_kernel,
                         cudaFuncAttributeMaxDynamicSharedMemorySize, SMEM_BYTES);
    topk_fused_kernel<<<rows, TPB, SMEM_BYTES>>>(x, kp, out);
}

// round 10
// speedup vs baseline: 1.8372x; 1.2164x over previous
#include <cuda_runtime.h>
#include <cstdint>

// TopK per row (B=4096 x D=65536 fp32, k=64), ReLU, scatter into zeros.
// One fused kernel, one CTA per row:
//   - Zero-fill of the output row is offloaded to TMA: 16 x cp.async.bulk
//     (16KB each) from a zeroed smem buffer -> ~16 instructions instead of
//     16384 STG.128 per CTA. Runs in background during the read loop.
//   - Hot loop: pure read stream (LDG.128, fully unrolled, imm offsets) +
//     FMNMX max-tree threshold detect + rare candidate push to smem.
//   - Exact rank of ~168 candidates, then scatter k winners after
//     cp.async.bulk.wait_group 0 (zero stores complete first).
// Exact 3-level radix fallback for arbitrary inputs (tie-break lowest index,
// matching jax.lax.top_k); never triggers on N(0,1) data (P < 1e-11/row).

namespace {

constexpr int TPB    = 512;
constexpr int D_DIM  = 65536;
constexpr int NV     = D_DIM / 4;       // 16384 float4 per row
constexpr int U      = 4;               // float4 per thread per iter
constexpr int ITERS  = NV / (TPB * U);  // 8
constexpr int CAP    = 2048;            // candidate capacity
constexpr float THRESH = 2.8f;          // E[cnt]~168 for N(0,1), >> k=64
constexpr int ZBYTES = 16 * 1024;       // zero buffer / TMA chunk
constexpr int NCHUNK = (D_DIM * 4) / ZBYTES;  // 16 chunks per 256KB row
constexpr unsigned SMEM_BYTES = ZBYTES + 2u * CAP * 4u;  // 32 KB dynamic

__device__ __forceinline__ unsigned orderKey(float f) {
    unsigned u = __float_as_uint(f);
    return u ^ ((u & 0x80000000u) ? 0xFFFFFFFFu : 0x80000000u);
}

__global__ void __launch_bounds__(TPB)
topk_tma_kernel(const float* __restrict__ x,
                const int* __restrict__ kptr,
                float* __restrict__ out)
{
    extern __shared__ unsigned smem_u[];
    unsigned* zbuf = smem_u;                               // [ZBYTES/4] zeros; hist alias in fallback
    float*    cval = reinterpret_cast<float*>(smem_u + ZBYTES / 4);  // [CAP]
    unsigned* cidx = smem_u + ZBYTES / 4 + CAP;            // [CAP]
    __shared__ unsigned s_cnt, s_bin, s_rank;
    __shared__ unsigned s_chunk[TPB + 1];

    const int tid = threadIdx.x;
    const int row = blockIdx.x;
    const unsigned k = (unsigned)__ldg(kptr);

    const float4* rowv = reinterpret_cast<const float4*>(x) + (size_t)row * NV;
    float*        outf = out + (size_t)row * D_DIM;

    // ---- Zero smem buffer, then launch background TMA zero stores ----
    for (int i = tid; i < ZBYTES / 4; i += TPB) zbuf[i] = 0u;
    if (tid == 0) s_cnt = 0u;
    asm volatile("fence.proxy.async.shared::cta;" ::: "memory");
    __syncthreads();

    if (tid == 0) {
        uint32_t zs;
        asm("{ .reg .u64 t; cvta.to.shared.u64 t, %1; cvt.u32.u64 %0, t; }"
            : "=r"(zs) : "l"(zbuf));
        #pragma unroll
        for (int c = 0; c < NCHUNK; ++c) {
            const char* dst = reinterpret_cast<const char*>(outf) + (size_t)c * ZBYTES;
            asm volatile(
                "cp.async.bulk.global.shared::cta.bulk_group [%0], [%1], %2;"
                :: "l"(dst), "r"(zs), "r"((unsigned)ZBYTES) : "memory");
        }
        asm volatile("cp.async.bulk.commit_group;" ::: "memory");
    }

    // ---- Hot pass: pure read stream + rare candidate collect ----
    #pragma unroll
    for (int it = 0; it < ITERS; ++it) {
        const int base = tid + it * TPB * U;
        float4 v[U];
        #pragma unroll
        for (int u = 0; u < U; ++u)
            v[u] = __ldcs(&rowv[base + u * TPB]);

        float m[U];
        #pragma unroll
        for (int u = 0; u < U; ++u)
            m[u] = fmaxf(fmaxf(v[u].x, v[u].y), fmaxf(v[u].z, v[u].w));

        bool any = (m[0] >= THRESH) | (m[1] >= THRESH) |
                   (m[2] >= THRESH) | (m[3] >= THRESH);
        if (any) {                                    // rare per thread
            #pragma unroll
            for (int u = 0; u < U; ++u) {
                if (m[u] >= THRESH) {
                    const int i = base + u * TPB;
                    float vv[4] = {v[u].x, v[u].y, v[u].z, v[u].w};
                    #pragma unroll
                    for (int l = 0; l < 4; ++l) {
                        if (vv[l] >= THRESH) {
                            unsigned p = atomicAdd(&s_cnt, 1u);
                            if (p < CAP) { cval[p] = vv[l]; cidx[p] = (unsigned)(i * 4 + l); }
                        }
                    }
                }
            }
        }
    }
    __syncthreads();

    // ---- Zero stores must land before any winner scatter ----
    if (tid == 0)
        asm volatile("cp.async.bulk.wait_group 0;" ::: "memory");
    __syncthreads();

    const unsigned cnt = s_cnt;
    if (cnt >= k && cnt <= CAP) {
        // exact rank among candidates; direct scatter
        for (unsigned j = (unsigned)tid; j < cnt; j += TPB) {
            const float    vj = cval[j];
            const unsigned ij = cidx[j];
            unsigned rank = 0;
            for (unsigned t = 0; t < cnt; ++t) {
                const float vt = cval[t];
                rank += (vt > vj) || (vt == vj && cidx[t] < ij);
            }
            if (rank < k)
                outf[ij] = fmaxf(vj, 0.0f);
        }
        return;
    }

    // ============== Exact fallback: 3-level radix refinement ==============
    // zbuf is free after wait_group -> reuse as 4096-bin histogram.
    unsigned* hist = zbuf;
    const float* rowf = reinterpret_cast<const float*>(rowv);
    unsigned need = k;
    unsigned b0, b1, b2;

    // level 0: bits[31:20]
    for (int i = tid; i < 4096; i += TPB) hist[i] = 0u;
    __syncthreads();
    for (int i = tid; i < D_DIM; i += TPB)
        atomicAdd(&hist[orderKey(rowf[i]) >> 20], 1u);
    __syncthreads();
    if (tid == 0) {
        unsigned acc = 0;
        for (int b = 4095; b >= 0; --b) {
            unsigned c = hist[b];
            if (acc + c >= need) { s_bin = (unsigned)b; s_rank = need - acc; break; }
            acc += c;
        }
    }
    __syncthreads();
    b0 = s_bin; need = s_rank;

    // level 1: bits[19:8] restricted to top bits == b0
    for (int i = tid; i < 4096; i += TPB) hist[i] = 0u;
    __syncthreads();
    for (int i = tid; i < D_DIM; i += TPB) {
        unsigned key = orderKey(rowf[i]);
        if ((key >> 20) == b0) atomicAdd(&hist[(key >> 8) & 0xFFFu], 1u);
    }
    __syncthreads();
    if (tid == 0) {
        unsigned acc = 0;
        for (int b = 4095; b >= 0; --b) {
            unsigned c = hist[b];
            if (acc + c >= need) { s_bin = (unsigned)b; s_rank = need - acc; break; }
            acc += c;
        }
    }
    __syncthreads();
    b1 = s_bin; need = s_rank;

    // level 2: bits[7:0] restricted to top 24 bits
    for (int i = tid; i < 256; i += TPB) hist[i] = 0u;
    __syncthreads();
    const unsigned pre24 = (b0 << 12) | b1;
    for (int i = tid; i < D_DIM; i += TPB) {
        unsigned key = orderKey(rowf[i]);
        if ((key >> 8) == pre24) atomicAdd(&hist[key & 0xFFu], 1u);
    }
    __syncthreads();
    if (tid == 0) {
        unsigned acc = 0;
        for (int b = 255; b >= 0; --b) {
            unsigned c = hist[b];
            if (acc + c >= need) { s_bin = (unsigned)b; s_rank = need - acc; break; }
            acc += c;
        }
    }
    __syncthreads();
    b2 = s_bin; need = s_rank;                    // take `need` of key==pivot
    const unsigned pivot = (pre24 << 8) | b2;

    // winners with key > pivot: write directly
    for (int i = tid; i < D_DIM; i += TPB) {
        float v = rowf[i];
        if (orderKey(v) > pivot)
            outf[i] = fmaxf(v, 0.0f);
    }

    // key == pivot: take `need` with the SMALLEST indices (jax tie rule)
    {
        const int CHUNK = D_DIM / TPB;   // 128
        unsigned local = 0;
        for (int i = tid * CHUNK; i < (tid + 1) * CHUNK; ++i)
            local += (orderKey(rowf[i]) == pivot);
        s_chunk[tid + 1] = local;
        if (tid == 0) s_chunk[0] = 0;
        __syncthreads();
        if (tid == 0)
            for (int t = 1; t <= TPB; ++t) s_chunk[t] += s_chunk[t - 1];
        __syncthreads();
        unsigned ord = s_chunk[tid];
        for (int i = tid * CHUNK; i < (tid + 1) * CHUNK; ++i) {
            float v = rowf[i];
            if (orderKey(v) == pivot) {
                if (ord < need)
                    outf[i] = fmaxf(v, 0.0f);
                ++ord;
            }
        }
    }
}

} // namespace

extern "C" void kernel_launch(void* const* d_in, const int* in_sizes, int n_in,
                              void* d_out, int out_size)
{
    const float* x   = (const float*)d_in[0];
    const int*   kp  = (const int*)d_in[1];
    float*       out = (float*)d_out;

    const int rows = in_sizes[0] / D_DIM;

    cudaFuncSetAttribute(topk_tma_kernel,
                         cudaFuncAttributeMaxDynamicSharedMemorySize, SMEM_BYTES);
    topk_tma_kernel<<<rows, TPB, SMEM_BYTES>>>(x, kp, out);
}